// round 12
// baseline (speedup 1.0000x reference)
#include <cuda_runtime.h>
#include <cuda_fp16.h>

#define NU 100000
#define NI 200000
#define NN 300000          // NU + NI
#define EMB 64
#define NE 1000000
#define BATCH 16384

#define SCAN_BS 1024
#define NSB ((NN + SCAN_BS - 1) / SCAN_BS)   // 293

// -------- scratch (device globals; zero-initialized at load) -------
// INVARIANT: every kernel_launch leaves g_cnt, g_flag2, g_n2 zeroed
// (consume-and-reset), so no zero pass is needed at the head.
__device__ int    g_cnt[NN];
__device__ int    g_scan[NN];
__device__ int    g_bsum[NSB];
__device__ int    g_off[NN + 1];
__device__ int    g_cursor[NN];
__device__ float  g_dinv[NN];
__device__ float  g_w[4];
__device__ float2 g_adj[2 * NE];           // {dst (int bits), edge weight}
__device__ __half g_h0[(size_t)NN * EMB];  // fp16 inputs
__device__ __half g_h1[(size_t)NN * EMB];  // layer 1
__device__ __half g_h2[(size_t)NN * EMB];  // layer 2
__device__ int    g_flag2[NN];
__device__ int    g_list2[NN];
__device__ int    g_n2;

// ------- fp32 -> fp16 conversion + softmax (side stream) -----------
__global__ void conv_kernel(const float* __restrict__ ue,
                            const float* __restrict__ ie,
                            const float* __restrict__ lw) {
    size_t i = (size_t)blockIdx.x * blockDim.x + threadIdx.x;
    const size_t total = (size_t)NN * EMB / 8;
    if (i == 0) {
        float m = lw[0];
        for (int k = 1; k < 4; k++) m = fmaxf(m, lw[k]);
        float s = 0.f, e[4];
        for (int k = 0; k < 4; k++) { e[k] = expf(lw[k] - m); s += e[k]; }
        for (int k = 0; k < 4; k++) g_w[k] = e[k] / s;
    }
    if (i >= total) return;
    size_t base = i * 8;
    const float4* s = (base < (size_t)NU * EMB)
        ? (const float4*)(ue + base)
        : (const float4*)(ie + (base - (size_t)NU * EMB));
    float4 a = s[0], b = s[1];
    __half2 c0 = __floats2half2_rn(a.x, a.y);
    __half2 c1 = __floats2half2_rn(a.z, a.w);
    __half2 c2 = __floats2half2_rn(b.x, b.y);
    __half2 c3 = __floats2half2_rn(b.z, b.w);
    uint4 o;
    o.x = *(unsigned*)&c0; o.y = *(unsigned*)&c1;
    o.z = *(unsigned*)&c2; o.w = *(unsigned*)&c3;
    ((uint4*)g_h0)[i] = o;
}

// ---------------- degree histogram (int4-vectorized) ---------------
// relies on g_cnt == 0 on entry (restored by scanC last call)
__global__ void hist_kernel(const int* __restrict__ eu,
                            const int* __restrict__ ei) {
    int i = blockIdx.x * blockDim.x + threadIdx.x;
    if (i >= NE / 4) return;
    int4 a = ((const int4*)eu)[i];
    int4 b = ((const int4*)ei)[i];
    atomicAdd(&g_cnt[a.x], 1);
    atomicAdd(&g_cnt[a.y], 1);
    atomicAdd(&g_cnt[a.z], 1);
    atomicAdd(&g_cnt[a.w], 1);
    atomicAdd(&g_cnt[NU + b.x], 1);
    atomicAdd(&g_cnt[NU + b.y], 1);
    atomicAdd(&g_cnt[NU + b.z], 1);
    atomicAdd(&g_cnt[NU + b.w], 1);
}

// ---------------- scans --------------------------------------------
__global__ void scanA_kernel() {
    __shared__ int ws[32];
    int tid = threadIdx.x;
    int i = blockIdx.x * SCAN_BS + tid;
    int lane = tid & 31, wid = tid >> 5;
    int v = (i < NN) ? g_cnt[i] : 0;
    int x = v;
    #pragma unroll
    for (int off = 1; off < 32; off <<= 1) {
        int t = __shfl_up_sync(0xffffffffu, x, off);
        if (lane >= off) x += t;
    }
    if (lane == 31) ws[wid] = x;
    __syncthreads();
    if (wid == 0) {
        int y = ws[lane];
        #pragma unroll
        for (int off = 1; off < 32; off <<= 1) {
            int t = __shfl_up_sync(0xffffffffu, y, off);
            if (lane >= off) y += t;
        }
        ws[lane] = y;
    }
    __syncthreads();
    if (wid > 0) x += ws[wid - 1];
    if (i < NN) g_scan[i] = x;
    if (tid == SCAN_BS - 1) g_bsum[blockIdx.x] = x;
}

// scanC: inline block-offset lookback + restores g_cnt = 0
__global__ void scanC_kernel() {
    __shared__ int s_boff;
    int tid = threadIdx.x;
    if (tid < 32) {
        int sum = 0;
        for (int k = tid; k < blockIdx.x; k += 32) sum += g_bsum[k];
        #pragma unroll
        for (int off = 16; off > 0; off >>= 1)
            sum += __shfl_down_sync(0xffffffffu, sum, off);
        if (tid == 0) s_boff = sum;
    }
    __syncthreads();
    int i = blockIdx.x * SCAN_BS + tid;
    if (i >= NN) return;
    int c = g_cnt[i];
    g_cnt[i] = 0;                       // reset for next call
    int excl = g_scan[i] - c + s_boff;
    g_off[i] = excl;
    g_cursor[i] = excl;
    g_dinv[i] = (c > 0) ? rsqrtf((float)c) : 0.f;
    if (i == NN - 1) g_off[NN] = excl + c;
}

__global__ void fill_kernel(const int* __restrict__ eu,
                            const int* __restrict__ ei) {
    int i = blockIdx.x * blockDim.x + threadIdx.x;
    if (i >= NE) return;
    int u = eu[i];
    int v = NU + ei[i];
    float w = g_dinv[u] * g_dinv[v];
    int p = atomicAdd(&g_cursor[u], 1);
    g_adj[p] = make_float2(__int_as_float(v), w);
    int q = atomicAdd(&g_cursor[v], 1);
    g_adj[q] = make_float2(__int_as_float(u), w);
}

// mark neighbors of batch nodes + the batch nodes themselves
__global__ void mark2_kernel(const int* __restrict__ uids,
                             const int* __restrict__ iids) {
    int idx = (blockIdx.x * blockDim.x + threadIdx.x) >> 5;
    if (idx >= BATCH) return;
    int lane = threadIdx.x & 31;
    int node = (lane < 16) ? uids[idx] : (NU + iids[idx]);
    int sub = lane & 15;
    int start = g_off[node], end = g_off[node + 1];
    for (int p = start + sub; p < end; p += 16) {
        int v = __float_as_int(g_adj[p].x);
        g_flag2[v] = 1;
    }
    if (sub == 0) g_flag2[node] = 1;
}

// compact + restore g_flag2 = 0
__global__ void compact2_kernel() {
    int i = blockIdx.x * blockDim.x + threadIdx.x;
    if (i >= NN) return;
    if (g_flag2[i]) {
        g_flag2[i] = 0;                 // reset for next call
        int p = atomicAdd(&g_n2, 1);
        g_list2[p] = i;
    }
}

// ---------------- fp16 gather core (8 lanes/node, uint4/lane) ------
__device__ __forceinline__ void acc_row8(const __half* __restrict__ prevH,
                                         int v, int sub, float w, float* acc) {
    uint4 p = ((const uint4*)(prevH + (size_t)v * EMB))[sub];
    float2 f0 = __half22float2(*(__half2*)&p.x);
    float2 f1 = __half22float2(*(__half2*)&p.y);
    float2 f2 = __half22float2(*(__half2*)&p.z);
    float2 f3 = __half22float2(*(__half2*)&p.w);
    acc[0] += w * f0.x; acc[1] += w * f0.y;
    acc[2] += w * f1.x; acc[3] += w * f1.y;
    acc[4] += w * f2.x; acc[5] += w * f2.y;
    acc[6] += w * f3.x; acc[7] += w * f3.y;
}

__device__ __forceinline__ void gather8(int node, int sub, unsigned mask,
                                        const __half* __restrict__ prevH,
                                        float* acc) {
    int start = g_off[node];
    int end   = g_off[node + 1];
    for (int base = start; base < end; base += 8) {
        int n = min(8, end - base);
        float2 e = make_float2(0.f, 0.f);
        if (sub < n) e = g_adj[base + sub];
        int   dr = __float_as_int(e.x);
        float wr = e.y;
        int j = 0;
        for (; j + 4 <= n; j += 4) {
            int   v0 = __shfl_sync(mask, dr, j + 0, 8);
            int   v1 = __shfl_sync(mask, dr, j + 1, 8);
            int   v2 = __shfl_sync(mask, dr, j + 2, 8);
            int   v3 = __shfl_sync(mask, dr, j + 3, 8);
            float w0 = __shfl_sync(mask, wr, j + 0, 8);
            float w1 = __shfl_sync(mask, wr, j + 1, 8);
            float w2 = __shfl_sync(mask, wr, j + 2, 8);
            float w3 = __shfl_sync(mask, wr, j + 3, 8);
            uint4 p0 = ((const uint4*)(prevH + (size_t)v0 * EMB))[sub];
            uint4 p1 = ((const uint4*)(prevH + (size_t)v1 * EMB))[sub];
            uint4 p2 = ((const uint4*)(prevH + (size_t)v2 * EMB))[sub];
            uint4 p3 = ((const uint4*)(prevH + (size_t)v3 * EMB))[sub];
            {
                float2 f0 = __half22float2(*(__half2*)&p0.x);
                float2 f1 = __half22float2(*(__half2*)&p0.y);
                float2 f2 = __half22float2(*(__half2*)&p0.z);
                float2 f3 = __half22float2(*(__half2*)&p0.w);
                acc[0] += w0 * f0.x; acc[1] += w0 * f0.y;
                acc[2] += w0 * f1.x; acc[3] += w0 * f1.y;
                acc[4] += w0 * f2.x; acc[5] += w0 * f2.y;
                acc[6] += w0 * f3.x; acc[7] += w0 * f3.y;
            }
            {
                float2 f0 = __half22float2(*(__half2*)&p1.x);
                float2 f1 = __half22float2(*(__half2*)&p1.y);
                float2 f2 = __half22float2(*(__half2*)&p1.z);
                float2 f3 = __half22float2(*(__half2*)&p1.w);
                acc[0] += w1 * f0.x; acc[1] += w1 * f0.y;
                acc[2] += w1 * f1.x; acc[3] += w1 * f1.y;
                acc[4] += w1 * f2.x; acc[5] += w1 * f2.y;
                acc[6] += w1 * f3.x; acc[7] += w1 * f3.y;
            }
            {
                float2 f0 = __half22float2(*(__half2*)&p2.x);
                float2 f1 = __half22float2(*(__half2*)&p2.y);
                float2 f2 = __half22float2(*(__half2*)&p2.z);
                float2 f3 = __half22float2(*(__half2*)&p2.w);
                acc[0] += w2 * f0.x; acc[1] += w2 * f0.y;
                acc[2] += w2 * f1.x; acc[3] += w2 * f1.y;
                acc[4] += w2 * f2.x; acc[5] += w2 * f2.y;
                acc[6] += w2 * f3.x; acc[7] += w2 * f3.y;
            }
            {
                float2 f0 = __half22float2(*(__half2*)&p3.x);
                float2 f1 = __half22float2(*(__half2*)&p3.y);
                float2 f2 = __half22float2(*(__half2*)&p3.z);
                float2 f3 = __half22float2(*(__half2*)&p3.w);
                acc[0] += w3 * f0.x; acc[1] += w3 * f0.y;
                acc[2] += w3 * f1.x; acc[3] += w3 * f1.y;
                acc[4] += w3 * f2.x; acc[5] += w3 * f2.y;
                acc[6] += w3 * f3.x; acc[7] += w3 * f3.y;
            }
        }
        for (; j < n; j++) {
            int   v = __shfl_sync(mask, dr, j, 8);
            float w = __shfl_sync(mask, wr, j, 8);
            acc_row8(prevH, v, sub, w, acc);
        }
    }
}

__device__ __forceinline__ void store_half8(__half* __restrict__ nextH,
                                            int node, int sub, const float* acc) {
    __half2 o0 = __floats2half2_rn(acc[0], acc[1]);
    __half2 o1 = __floats2half2_rn(acc[2], acc[3]);
    __half2 o2 = __floats2half2_rn(acc[4], acc[5]);
    __half2 o3 = __floats2half2_rn(acc[6], acc[7]);
    uint4 o;
    o.x = *(unsigned*)&o0; o.y = *(unsigned*)&o1;
    o.z = *(unsigned*)&o2; o.w = *(unsigned*)&o3;
    ((uint4*)(nextH + (size_t)node * EMB))[sub] = o;
}

__global__ void prop_full_kernel(const __half* __restrict__ prevH,
                                 __half* __restrict__ nextH) {
    int warpId = (blockIdx.x * blockDim.x + threadIdx.x) >> 5;
    int lane = threadIdx.x & 31;
    int quad = lane >> 3;
    int sub  = lane & 7;
    int node = warpId * 4 + quad;
    if (node >= NN) return;
    unsigned mask = 0xFFu << (quad * 8);
    float acc[8] = {0.f,0.f,0.f,0.f,0.f,0.f,0.f,0.f};
    gather8(node, sub, mask, prevH, acc);
    store_half8(nextH, node, sub, acc);
}

__global__ void prop_list_kernel(const __half* __restrict__ prevH,
                                 __half* __restrict__ nextH,
                                 const int* __restrict__ list,
                                 const int* __restrict__ count) {
    int warpId = (blockIdx.x * blockDim.x + threadIdx.x) >> 5;
    int lane = threadIdx.x & 31;
    int cnt = __shfl_sync(0xffffffffu, (lane == 0) ? *count : 0, 0);
    int quad = lane >> 3;
    int sub  = lane & 7;
    int idx = warpId * 4 + quad;
    if (idx >= cnt) return;
    int node = list[idx];
    unsigned mask = 0xFFu << (quad * 8);
    float acc[8] = {0.f,0.f,0.f,0.f,0.f,0.f,0.f,0.f};
    gather8(node, sub, mask, prevH, acc);
    store_half8(nextH, node, sub, acc);
}

// --------------- fused layer-3 + score (+ resets g_n2) -------------
__global__ void score_kernel(const int* __restrict__ uids,
                             const int* __restrict__ iids,
                             const float* __restrict__ ue,
                             const float* __restrict__ ie,
                             float* __restrict__ out) {
    int gt = blockIdx.x * blockDim.x + threadIdx.x;
    if (gt == 0) g_n2 = 0;              // reset for next call (prop_list already consumed it)
    int grpG = gt >> 3;
    int sub  = gt & 7;
    int pair = grpG >> 1;
    int side = grpG & 1;
    if (pair >= BATCH) return;
    int lane = threadIdx.x & 31;
    int grp = lane >> 3;
    unsigned gmask = 0xFFu << (grp * 8);

    int node;
    const float4* r0;
    if (side == 0) {
        int u = uids[pair];
        node = u;
        r0 = (const float4*)(ue + (size_t)u * EMB);
    } else {
        int v = iids[pair];
        node = NU + v;
        r0 = (const float4*)(ie + (size_t)v * EMB);
    }

    float w0 = g_w[0], w1 = g_w[1], w2 = g_w[2], w3 = g_w[3];

    float a3[8] = {0.f,0.f,0.f,0.f,0.f,0.f,0.f,0.f};
    gather8(node, sub, gmask, g_h2, a3);

    float4 pa = r0[sub * 2];
    float4 pb = r0[sub * 2 + 1];
    uint4 x1 = ((const uint4*)(g_h1 + (size_t)node * EMB))[sub];
    uint4 x2 = ((const uint4*)(g_h2 + (size_t)node * EMB))[sub];
    float2 l1a = __half22float2(*(__half2*)&x1.x);
    float2 l1b = __half22float2(*(__half2*)&x1.y);
    float2 l1c = __half22float2(*(__half2*)&x1.z);
    float2 l1d = __half22float2(*(__half2*)&x1.w);
    float2 l2a = __half22float2(*(__half2*)&x2.x);
    float2 l2b = __half22float2(*(__half2*)&x2.y);
    float2 l2c = __half22float2(*(__half2*)&x2.z);
    float2 l2d = __half22float2(*(__half2*)&x2.w);

    float f[8];
    f[0] = w0 * pa.x + w1 * l1a.x + w2 * l2a.x + w3 * a3[0];
    f[1] = w0 * pa.y + w1 * l1a.y + w2 * l2a.y + w3 * a3[1];
    f[2] = w0 * pa.z + w1 * l1b.x + w2 * l2b.x + w3 * a3[2];
    f[3] = w0 * pa.w + w1 * l1b.y + w2 * l2b.y + w3 * a3[3];
    f[4] = w0 * pb.x + w1 * l1c.x + w2 * l2c.x + w3 * a3[4];
    f[5] = w0 * pb.y + w1 * l1c.y + w2 * l2c.y + w3 * a3[5];
    f[6] = w0 * pb.z + w1 * l1d.x + w2 * l2d.x + w3 * a3[6];
    f[7] = w0 * pb.w + w1 * l1d.y + w2 * l2d.y + w3 * a3[7];

    float dp = 0.f;
    #pragma unroll
    for (int k = 0; k < 8; k++) {
        float other = __shfl_xor_sync(0xffffffffu, f[k], 8);
        dp += f[k] * other;
    }
    dp += __shfl_down_sync(0xffffffffu, dp, 4, 8);
    dp += __shfl_down_sync(0xffffffffu, dp, 2, 8);
    dp += __shfl_down_sync(0xffffffffu, dp, 1, 8);
    if (side == 0 && sub == 0) out[pair] = dp;
}

// ------------------------- launcher --------------------------------
extern "C" void kernel_launch(void* const* d_in, const int* in_sizes, int n_in,
                              void* d_out, int out_size) {
    const float* user_emb = (const float*)d_in[0];
    const float* item_emb = (const float*)d_in[1];
    const float* layer_w  = (const float*)d_in[2];
    const int*   eu       = (const int*)d_in[3];
    const int*   ei       = (const int*)d_in[4];
    const int*   uids     = (const int*)d_in[5];
    const int*   iids     = (const int*)d_in[6];
    float*       out      = (float*)d_out;
    (void)in_sizes; (void)n_in; (void)out_size;

    __half *h0, *h1, *h2;
    int *list2, *n2;
    cudaGetSymbolAddress((void**)&h0, g_h0);
    cudaGetSymbolAddress((void**)&h1, g_h1);
    cudaGetSymbolAddress((void**)&h2, g_h2);
    cudaGetSymbolAddress((void**)&list2, g_list2);
    cudaGetSymbolAddress((void**)&n2, g_n2);

    cudaStream_t s1;
    cudaStreamCreateWithFlags(&s1, cudaStreamNonBlocking);
    cudaEvent_t evFork, evConv, evFill, evMark;
    cudaEventCreateWithFlags(&evFork, cudaEventDisableTiming);
    cudaEventCreateWithFlags(&evConv, cudaEventDisableTiming);
    cudaEventCreateWithFlags(&evFill, cudaEventDisableTiming);
    cudaEventCreateWithFlags(&evMark, cudaEventDisableTiming);

    // ---- fork side stream immediately: fp16 conversion + softmax ----
    cudaEventRecord(evFork, 0);
    cudaStreamWaitEvent(s1, evFork, 0);
    const size_t CONV_T = (size_t)NN * EMB / 8;
    conv_kernel<<<(int)((CONV_T + 255) / 256), 256, 0, s1>>>(user_emb, item_emb, layer_w);
    cudaEventRecord(evConv, s1);

    // ---- CSR chain on main stream (g_cnt already zero) ----
    hist_kernel<<<(NE / 4 + 255) / 256, 256>>>(eu, ei);
    scanA_kernel<<<NSB, SCAN_BS>>>();
    scanC_kernel<<<NSB, SCAN_BS>>>();
    fill_kernel<<<(NE + 255) / 256, 256>>>(eu, ei);
    cudaEventRecord(evFill, 0);

    // ---- frontier branch on side stream (overlaps prop_full) ----
    cudaStreamWaitEvent(s1, evFill, 0);
    mark2_kernel<<<(BATCH * 32 + 255) / 256, 256, 0, s1>>>(uids, iids);
    compact2_kernel<<<(NN + 255) / 256, 256, 0, s1>>>();
    cudaEventRecord(evMark, s1);

    // ---- propagation ----
    cudaStreamWaitEvent(0, evConv, 0);
    const int FULL_BLOCKS = ((NN + 3) / 4 * 32 + 255) / 256;
    prop_full_kernel<<<FULL_BLOCKS, 256>>>(h0, h1);
    cudaStreamWaitEvent(0, evMark, 0);
    prop_list_kernel<<<FULL_BLOCKS, 256>>>(h1, h2, list2, n2);

    // ---- fused layer-3 + scores (also resets g_n2) ----
    score_kernel<<<(BATCH * 16 + 255) / 256, 256>>>(uids, iids, user_emb, item_emb, out);

    cudaEventDestroy(evFork);
    cudaEventDestroy(evConv);
    cudaEventDestroy(evFill);
    cudaEventDestroy(evMark);
    cudaStreamDestroy(s1);
}

// round 13
// speedup vs baseline: 1.0049x; 1.0049x over previous
#include <cuda_runtime.h>
#include <cuda_fp16.h>

#define NU 100000
#define NI 200000
#define NN 300000          // NU + NI
#define EMB 64
#define NE 1000000
#define BATCH 16384

#define SCAN_BS 1024
#define NSB ((NN + SCAN_BS - 1) / SCAN_BS)   // 293

// -------- scratch (device globals; zero-initialized at load) -------
// INVARIANT: every kernel_launch leaves g_cnt, g_flag2, g_n2, g_total
// zeroed (consume-and-reset), so no zero pass is needed at the head.
__device__ int    g_cnt[NN];
__device__ int    g_total;                 // adjacency cursor
__device__ int2   g_range[NN];             // {start, end} per node (unordered regions)
__device__ int    g_cursor[NN];
__device__ float  g_dinv[NN];
__device__ float  g_w[4];
__device__ float2 g_adj[2 * NE];           // {dst (int bits), edge weight}
__device__ __half g_h0[(size_t)NN * EMB];  // fp16 inputs
__device__ __half g_h1[(size_t)NN * EMB];  // layer 1
__device__ __half g_h2[(size_t)NN * EMB];  // layer 2
__device__ int    g_flag2[NN];
__device__ int    g_list2[NN];
__device__ int    g_n2;

// ------- fp32 -> fp16 conversion + softmax (side stream) -----------
__global__ void conv_kernel(const float* __restrict__ ue,
                            const float* __restrict__ ie,
                            const float* __restrict__ lw) {
    size_t i = (size_t)blockIdx.x * blockDim.x + threadIdx.x;
    const size_t total = (size_t)NN * EMB / 8;
    if (i == 0) {
        float m = lw[0];
        for (int k = 1; k < 4; k++) m = fmaxf(m, lw[k]);
        float s = 0.f, e[4];
        for (int k = 0; k < 4; k++) { e[k] = expf(lw[k] - m); s += e[k]; }
        for (int k = 0; k < 4; k++) g_w[k] = e[k] / s;
    }
    if (i >= total) return;
    size_t base = i * 8;
    const float4* s = (base < (size_t)NU * EMB)
        ? (const float4*)(ue + base)
        : (const float4*)(ie + (base - (size_t)NU * EMB));
    float4 a = s[0], b = s[1];
    __half2 c0 = __floats2half2_rn(a.x, a.y);
    __half2 c1 = __floats2half2_rn(a.z, a.w);
    __half2 c2 = __floats2half2_rn(b.x, b.y);
    __half2 c3 = __floats2half2_rn(b.z, b.w);
    uint4 o;
    o.x = *(unsigned*)&c0; o.y = *(unsigned*)&c1;
    o.z = *(unsigned*)&c2; o.w = *(unsigned*)&c3;
    ((uint4*)g_h0)[i] = o;
}

// ---------------- degree histogram (int4-vectorized) ---------------
__global__ void hist_kernel(const int* __restrict__ eu,
                            const int* __restrict__ ei) {
    int i = blockIdx.x * blockDim.x + threadIdx.x;
    if (i >= NE / 4) return;
    int4 a = ((const int4*)eu)[i];
    int4 b = ((const int4*)ei)[i];
    atomicAdd(&g_cnt[a.x], 1);
    atomicAdd(&g_cnt[a.y], 1);
    atomicAdd(&g_cnt[a.z], 1);
    atomicAdd(&g_cnt[a.w], 1);
    atomicAdd(&g_cnt[NU + b.x], 1);
    atomicAdd(&g_cnt[NU + b.y], 1);
    atomicAdd(&g_cnt[NU + b.z], 1);
    atomicAdd(&g_cnt[NU + b.w], 1);
}

// -------- offsets: block scan + atomic block base (one kernel) -----
// Regions need not be ordered by node id; each block grabs a disjoint
// chunk of g_adj via one atomicAdd. Also resets g_cnt.
__global__ void offsets_kernel() {
    __shared__ int ws[32];
    __shared__ int s_base;
    int tid = threadIdx.x;
    int i = blockIdx.x * SCAN_BS + tid;
    int lane = tid & 31, wid = tid >> 5;
    int c = (i < NN) ? g_cnt[i] : 0;
    int x = c;
    #pragma unroll
    for (int off = 1; off < 32; off <<= 1) {
        int t = __shfl_up_sync(0xffffffffu, x, off);
        if (lane >= off) x += t;
    }
    if (lane == 31) ws[wid] = x;
    __syncthreads();
    if (wid == 0) {
        int y = ws[lane];
        #pragma unroll
        for (int off = 1; off < 32; off <<= 1) {
            int t = __shfl_up_sync(0xffffffffu, y, off);
            if (lane >= off) y += t;
        }
        ws[lane] = y;
    }
    __syncthreads();
    int incl = x + ((wid > 0) ? ws[wid - 1] : 0);
    if (tid == SCAN_BS - 1) s_base = atomicAdd(&g_total, incl);
    __syncthreads();
    if (i < NN) {
        int start = s_base + incl - c;
        g_range[i] = make_int2(start, start + c);
        g_cursor[i] = start;
        g_dinv[i] = (c > 0) ? rsqrtf((float)c) : 0.f;
        g_cnt[i] = 0;                   // reset for next call
    }
}

// fill adjacency; also resets g_total (consumed by offsets already)
__global__ void fill_kernel(const int* __restrict__ eu,
                            const int* __restrict__ ei) {
    int i = blockIdx.x * blockDim.x + threadIdx.x;
    if (i == 0) g_total = 0;            // reset for next call
    if (i >= NE) return;
    int u = eu[i];
    int v = NU + ei[i];
    float w = g_dinv[u] * g_dinv[v];
    int p = atomicAdd(&g_cursor[u], 1);
    g_adj[p] = make_float2(__int_as_float(v), w);
    int q = atomicAdd(&g_cursor[v], 1);
    g_adj[q] = make_float2(__int_as_float(u), w);
}

// mark neighbors of batch nodes + the batch nodes themselves
__global__ void mark2_kernel(const int* __restrict__ uids,
                             const int* __restrict__ iids) {
    int idx = (blockIdx.x * blockDim.x + threadIdx.x) >> 5;
    if (idx >= BATCH) return;
    int lane = threadIdx.x & 31;
    int node = (lane < 16) ? uids[idx] : (NU + iids[idx]);
    int sub = lane & 15;
    int2 r = g_range[node];
    for (int p = r.x + sub; p < r.y; p += 16) {
        int v = __float_as_int(g_adj[p].x);
        g_flag2[v] = 1;
    }
    if (sub == 0) g_flag2[node] = 1;
}

// compact + restore g_flag2 = 0
__global__ void compact2_kernel() {
    int i = blockIdx.x * blockDim.x + threadIdx.x;
    if (i >= NN) return;
    if (g_flag2[i]) {
        g_flag2[i] = 0;                 // reset for next call
        int p = atomicAdd(&g_n2, 1);
        g_list2[p] = i;
    }
}

// ---------------- fp16 gather core (8 lanes/node, uint4/lane) ------
__device__ __forceinline__ void acc_row8(const __half* __restrict__ prevH,
                                         int v, int sub, float w, float* acc) {
    uint4 p = ((const uint4*)(prevH + (size_t)v * EMB))[sub];
    float2 f0 = __half22float2(*(__half2*)&p.x);
    float2 f1 = __half22float2(*(__half2*)&p.y);
    float2 f2 = __half22float2(*(__half2*)&p.z);
    float2 f3 = __half22float2(*(__half2*)&p.w);
    acc[0] += w * f0.x; acc[1] += w * f0.y;
    acc[2] += w * f1.x; acc[3] += w * f1.y;
    acc[4] += w * f2.x; acc[5] += w * f2.y;
    acc[6] += w * f3.x; acc[7] += w * f3.y;
}

__device__ __forceinline__ void gather8(int node, int sub, unsigned mask,
                                        const __half* __restrict__ prevH,
                                        float* acc) {
    int2 r = g_range[node];
    int start = r.x, end = r.y;
    for (int base = start; base < end; base += 8) {
        int n = min(8, end - base);
        float2 e = make_float2(0.f, 0.f);
        if (sub < n) e = g_adj[base + sub];
        int   dr = __float_as_int(e.x);
        float wr = e.y;
        int j = 0;
        for (; j + 4 <= n; j += 4) {
            int   v0 = __shfl_sync(mask, dr, j + 0, 8);
            int   v1 = __shfl_sync(mask, dr, j + 1, 8);
            int   v2 = __shfl_sync(mask, dr, j + 2, 8);
            int   v3 = __shfl_sync(mask, dr, j + 3, 8);
            float w0 = __shfl_sync(mask, wr, j + 0, 8);
            float w1 = __shfl_sync(mask, wr, j + 1, 8);
            float w2 = __shfl_sync(mask, wr, j + 2, 8);
            float w3 = __shfl_sync(mask, wr, j + 3, 8);
            uint4 p0 = ((const uint4*)(prevH + (size_t)v0 * EMB))[sub];
            uint4 p1 = ((const uint4*)(prevH + (size_t)v1 * EMB))[sub];
            uint4 p2 = ((const uint4*)(prevH + (size_t)v2 * EMB))[sub];
            uint4 p3 = ((const uint4*)(prevH + (size_t)v3 * EMB))[sub];
            {
                float2 f0 = __half22float2(*(__half2*)&p0.x);
                float2 f1 = __half22float2(*(__half2*)&p0.y);
                float2 f2 = __half22float2(*(__half2*)&p0.z);
                float2 f3 = __half22float2(*(__half2*)&p0.w);
                acc[0] += w0 * f0.x; acc[1] += w0 * f0.y;
                acc[2] += w0 * f1.x; acc[3] += w0 * f1.y;
                acc[4] += w0 * f2.x; acc[5] += w0 * f2.y;
                acc[6] += w0 * f3.x; acc[7] += w0 * f3.y;
            }
            {
                float2 f0 = __half22float2(*(__half2*)&p1.x);
                float2 f1 = __half22float2(*(__half2*)&p1.y);
                float2 f2 = __half22float2(*(__half2*)&p1.z);
                float2 f3 = __half22float2(*(__half2*)&p1.w);
                acc[0] += w1 * f0.x; acc[1] += w1 * f0.y;
                acc[2] += w1 * f1.x; acc[3] += w1 * f1.y;
                acc[4] += w1 * f2.x; acc[5] += w1 * f2.y;
                acc[6] += w1 * f3.x; acc[7] += w1 * f3.y;
            }
            {
                float2 f0 = __half22float2(*(__half2*)&p2.x);
                float2 f1 = __half22float2(*(__half2*)&p2.y);
                float2 f2 = __half22float2(*(__half2*)&p2.z);
                float2 f3 = __half22float2(*(__half2*)&p2.w);
                acc[0] += w2 * f0.x; acc[1] += w2 * f0.y;
                acc[2] += w2 * f1.x; acc[3] += w2 * f1.y;
                acc[4] += w2 * f2.x; acc[5] += w2 * f2.y;
                acc[6] += w2 * f3.x; acc[7] += w2 * f3.y;
            }
            {
                float2 f0 = __half22float2(*(__half2*)&p3.x);
                float2 f1 = __half22float2(*(__half2*)&p3.y);
                float2 f2 = __half22float2(*(__half2*)&p3.z);
                float2 f3 = __half22float2(*(__half2*)&p3.w);
                acc[0] += w3 * f0.x; acc[1] += w3 * f0.y;
                acc[2] += w3 * f1.x; acc[3] += w3 * f1.y;
                acc[4] += w3 * f2.x; acc[5] += w3 * f2.y;
                acc[6] += w3 * f3.x; acc[7] += w3 * f3.y;
            }
        }
        for (; j < n; j++) {
            int   v = __shfl_sync(mask, dr, j, 8);
            float w = __shfl_sync(mask, wr, j, 8);
            acc_row8(prevH, v, sub, w, acc);
        }
    }
}

__device__ __forceinline__ void store_half8(__half* __restrict__ nextH,
                                            int node, int sub, const float* acc) {
    __half2 o0 = __floats2half2_rn(acc[0], acc[1]);
    __half2 o1 = __floats2half2_rn(acc[2], acc[3]);
    __half2 o2 = __floats2half2_rn(acc[4], acc[5]);
    __half2 o3 = __floats2half2_rn(acc[6], acc[7]);
    uint4 o;
    o.x = *(unsigned*)&o0; o.y = *(unsigned*)&o1;
    o.z = *(unsigned*)&o2; o.w = *(unsigned*)&o3;
    ((uint4*)(nextH + (size_t)node * EMB))[sub] = o;
}

__global__ void prop_full_kernel(const __half* __restrict__ prevH,
                                 __half* __restrict__ nextH) {
    int warpId = (blockIdx.x * blockDim.x + threadIdx.x) >> 5;
    int lane = threadIdx.x & 31;
    int quad = lane >> 3;
    int sub  = lane & 7;
    int node = warpId * 4 + quad;
    if (node >= NN) return;
    unsigned mask = 0xFFu << (quad * 8);
    float acc[8] = {0.f,0.f,0.f,0.f,0.f,0.f,0.f,0.f};
    gather8(node, sub, mask, prevH, acc);
    store_half8(nextH, node, sub, acc);
}

__global__ void prop_list_kernel(const __half* __restrict__ prevH,
                                 __half* __restrict__ nextH,
                                 const int* __restrict__ list,
                                 const int* __restrict__ count) {
    int warpId = (blockIdx.x * blockDim.x + threadIdx.x) >> 5;
    int lane = threadIdx.x & 31;
    int cnt = __shfl_sync(0xffffffffu, (lane == 0) ? *count : 0, 0);
    int quad = lane >> 3;
    int sub  = lane & 7;
    int idx = warpId * 4 + quad;
    if (idx >= cnt) return;
    int node = list[idx];
    unsigned mask = 0xFFu << (quad * 8);
    float acc[8] = {0.f,0.f,0.f,0.f,0.f,0.f,0.f,0.f};
    gather8(node, sub, mask, prevH, acc);
    store_half8(nextH, node, sub, acc);
}

// --------------- fused layer-3 + score (+ resets g_n2) -------------
__global__ void score_kernel(const int* __restrict__ uids,
                             const int* __restrict__ iids,
                             const float* __restrict__ ue,
                             const float* __restrict__ ie,
                             float* __restrict__ out) {
    int gt = blockIdx.x * blockDim.x + threadIdx.x;
    if (gt == 0) g_n2 = 0;              // reset for next call
    int grpG = gt >> 3;
    int sub  = gt & 7;
    int pair = grpG >> 1;
    int side = grpG & 1;
    if (pair >= BATCH) return;
    int lane = threadIdx.x & 31;
    int grp = lane >> 3;
    unsigned gmask = 0xFFu << (grp * 8);

    int node;
    const float4* r0;
    if (side == 0) {
        int u = uids[pair];
        node = u;
        r0 = (const float4*)(ue + (size_t)u * EMB);
    } else {
        int v = iids[pair];
        node = NU + v;
        r0 = (const float4*)(ie + (size_t)v * EMB);
    }

    float w0 = g_w[0], w1 = g_w[1], w2 = g_w[2], w3 = g_w[3];

    float a3[8] = {0.f,0.f,0.f,0.f,0.f,0.f,0.f,0.f};
    gather8(node, sub, gmask, g_h2, a3);

    float4 pa = r0[sub * 2];
    float4 pb = r0[sub * 2 + 1];
    uint4 x1 = ((const uint4*)(g_h1 + (size_t)node * EMB))[sub];
    uint4 x2 = ((const uint4*)(g_h2 + (size_t)node * EMB))[sub];
    float2 l1a = __half22float2(*(__half2*)&x1.x);
    float2 l1b = __half22float2(*(__half2*)&x1.y);
    float2 l1c = __half22float2(*(__half2*)&x1.z);
    float2 l1d = __half22float2(*(__half2*)&x1.w);
    float2 l2a = __half22float2(*(__half2*)&x2.x);
    float2 l2b = __half22float2(*(__half2*)&x2.y);
    float2 l2c = __half22float2(*(__half2*)&x2.z);
    float2 l2d = __half22float2(*(__half2*)&x2.w);

    float f[8];
    f[0] = w0 * pa.x + w1 * l1a.x + w2 * l2a.x + w3 * a3[0];
    f[1] = w0 * pa.y + w1 * l1a.y + w2 * l2a.y + w3 * a3[1];
    f[2] = w0 * pa.z + w1 * l1b.x + w2 * l2b.x + w3 * a3[2];
    f[3] = w0 * pa.w + w1 * l1b.y + w2 * l2b.y + w3 * a3[3];
    f[4] = w0 * pb.x + w1 * l1c.x + w2 * l2c.x + w3 * a3[4];
    f[5] = w0 * pb.y + w1 * l1c.y + w2 * l2c.y + w3 * a3[5];
    f[6] = w0 * pb.z + w1 * l1d.x + w2 * l2d.x + w3 * a3[6];
    f[7] = w0 * pb.w + w1 * l1d.y + w2 * l2d.y + w3 * a3[7];

    float dp = 0.f;
    #pragma unroll
    for (int k = 0; k < 8; k++) {
        float other = __shfl_xor_sync(0xffffffffu, f[k], 8);
        dp += f[k] * other;
    }
    dp += __shfl_down_sync(0xffffffffu, dp, 4, 8);
    dp += __shfl_down_sync(0xffffffffu, dp, 2, 8);
    dp += __shfl_down_sync(0xffffffffu, dp, 1, 8);
    if (side == 0 && sub == 0) out[pair] = dp;
}

// ------------------------- launcher --------------------------------
extern "C" void kernel_launch(void* const* d_in, const int* in_sizes, int n_in,
                              void* d_out, int out_size) {
    const float* user_emb = (const float*)d_in[0];
    const float* item_emb = (const float*)d_in[1];
    const float* layer_w  = (const float*)d_in[2];
    const int*   eu       = (const int*)d_in[3];
    const int*   ei       = (const int*)d_in[4];
    const int*   uids     = (const int*)d_in[5];
    const int*   iids     = (const int*)d_in[6];
    float*       out      = (float*)d_out;
    (void)in_sizes; (void)n_in; (void)out_size;

    __half *h0, *h1, *h2;
    int *list2, *n2;
    cudaGetSymbolAddress((void**)&h0, g_h0);
    cudaGetSymbolAddress((void**)&h1, g_h1);
    cudaGetSymbolAddress((void**)&h2, g_h2);
    cudaGetSymbolAddress((void**)&list2, g_list2);
    cudaGetSymbolAddress((void**)&n2, g_n2);

    cudaStream_t s1;
    cudaStreamCreateWithFlags(&s1, cudaStreamNonBlocking);
    cudaEvent_t evFork, evConv, evFill, evMark;
    cudaEventCreateWithFlags(&evFork, cudaEventDisableTiming);
    cudaEventCreateWithFlags(&evConv, cudaEventDisableTiming);
    cudaEventCreateWithFlags(&evFill, cudaEventDisableTiming);
    cudaEventCreateWithFlags(&evMark, cudaEventDisableTiming);

    // ---- fork side stream immediately: fp16 conversion + softmax ----
    cudaEventRecord(evFork, 0);
    cudaStreamWaitEvent(s1, evFork, 0);
    const size_t CONV_T = (size_t)NN * EMB / 8;
    conv_kernel<<<(int)((CONV_T + 255) / 256), 256, 0, s1>>>(user_emb, item_emb, layer_w);
    cudaEventRecord(evConv, s1);

    // ---- CSR chain on main stream (g_cnt already zero) ----
    hist_kernel<<<(NE / 4 + 255) / 256, 256>>>(eu, ei);
    offsets_kernel<<<NSB, SCAN_BS>>>();
    fill_kernel<<<(NE + 255) / 256, 256>>>(eu, ei);
    cudaEventRecord(evFill, 0);

    // ---- frontier branch on side stream (overlaps prop_full) ----
    cudaStreamWaitEvent(s1, evFill, 0);
    mark2_kernel<<<(BATCH * 32 + 255) / 256, 256, 0, s1>>>(uids, iids);
    compact2_kernel<<<(NN + 255) / 256, 256, 0, s1>>>();
    cudaEventRecord(evMark, s1);

    // ---- propagation ----
    cudaStreamWaitEvent(0, evConv, 0);
    const int FULL_BLOCKS = ((NN + 3) / 4 * 32 + 255) / 256;
    prop_full_kernel<<<FULL_BLOCKS, 256>>>(h0, h1);
    cudaStreamWaitEvent(0, evMark, 0);
    prop_list_kernel<<<FULL_BLOCKS, 256>>>(h1, h2, list2, n2);

    // ---- fused layer-3 + scores (also resets g_n2) ----
    score_kernel<<<(BATCH * 16 + 255) / 256, 256>>>(uids, iids, user_emb, item_emb, out);

    cudaEventDestroy(evFork);
    cudaEventDestroy(evConv);
    cudaEventDestroy(evFill);
    cudaEventDestroy(evMark);
    cudaStreamDestroy(s1);
}

// round 14
// speedup vs baseline: 1.0684x; 1.0632x over previous
#include <cuda_runtime.h>
#include <cuda_fp16.h>

#define NU 100000
#define NI 200000
#define NN 300000          // NU + NI
#define EMB 64
#define NE 1000000
#define BATCH 16384

#define SCAN_BS 1024
#define NSB ((NN + SCAN_BS - 1) / SCAN_BS)   // 293

// -------- scratch (device globals; zero-initialized at load) -------
// INVARIANT: every kernel_launch leaves g_cnt, g_flag2, g_n2, g_total
// zeroed (consume-and-reset), so no zero pass is needed at the head.
__device__ int    g_cnt[NN];
__device__ int    g_total;                 // adjacency cursor (offsets kernel)
__device__ int2   g_range[NN];             // {start, end} per node
__device__ float  g_dinv[NN];
__device__ float  g_w[4];
__device__ int    g_rankU[NE];             // edge rank in user list (from hist)
__device__ int    g_rankV[NE];             // edge rank in item list (from hist)
__device__ int    g_adj[2 * NE];           // dst node only (weightless!)
__device__ __half g_h0[(size_t)NN * EMB];  // fp16 inputs -> scaled s0 in place
__device__ __half g_h1[(size_t)NN * EMB];  // s1 = dinv .* e1
__device__ __half g_h2[(size_t)NN * EMB];  // s2 = dinv .* e2
__device__ int    g_flag2[NN];
__device__ int    g_list2[NN];
__device__ int    g_n2;

// ------- fp32 -> fp16 conversion + softmax (side stream) -----------
__global__ void conv_kernel(const float* __restrict__ ue,
                            const float* __restrict__ ie,
                            const float* __restrict__ lw) {
    size_t i = (size_t)blockIdx.x * blockDim.x + threadIdx.x;
    const size_t total = (size_t)NN * EMB / 8;
    if (i == 0) {
        float m = lw[0];
        for (int k = 1; k < 4; k++) m = fmaxf(m, lw[k]);
        float s = 0.f, e[4];
        for (int k = 0; k < 4; k++) { e[k] = expf(lw[k] - m); s += e[k]; }
        for (int k = 0; k < 4; k++) g_w[k] = e[k] / s;
    }
    if (i >= total) return;
    size_t base = i * 8;
    const float4* s = (base < (size_t)NU * EMB)
        ? (const float4*)(ue + base)
        : (const float4*)(ie + (base - (size_t)NU * EMB));
    float4 a = s[0], b = s[1];
    __half2 c0 = __floats2half2_rn(a.x, a.y);
    __half2 c1 = __floats2half2_rn(a.z, a.w);
    __half2 c2 = __floats2half2_rn(b.x, b.y);
    __half2 c3 = __floats2half2_rn(b.z, b.w);
    uint4 o;
    o.x = *(unsigned*)&c0; o.y = *(unsigned*)&c1;
    o.z = *(unsigned*)&c2; o.w = *(unsigned*)&c3;
    ((uint4*)g_h0)[i] = o;
}

// ------- in-place scale: h0 *= dinv[node]  (side stream) -----------
__global__ void scale_kernel() {
    size_t i = (size_t)blockIdx.x * blockDim.x + threadIdx.x;
    const size_t total = (size_t)NN * EMB / 8;
    if (i >= total) return;
    int node = (int)(i >> 3);              // 8 uint4 per 64-half row
    float d = g_dinv[node];
    uint4 x = ((uint4*)g_h0)[i];
    float2 f0 = __half22float2(*(__half2*)&x.x);
    float2 f1 = __half22float2(*(__half2*)&x.y);
    float2 f2 = __half22float2(*(__half2*)&x.z);
    float2 f3 = __half22float2(*(__half2*)&x.w);
    __half2 o0 = __floats2half2_rn(d * f0.x, d * f0.y);
    __half2 o1 = __floats2half2_rn(d * f1.x, d * f1.y);
    __half2 o2 = __floats2half2_rn(d * f2.x, d * f2.y);
    __half2 o3 = __floats2half2_rn(d * f3.x, d * f3.y);
    uint4 o;
    o.x = *(unsigned*)&o0; o.y = *(unsigned*)&o1;
    o.z = *(unsigned*)&o2; o.w = *(unsigned*)&o3;
    ((uint4*)g_h0)[i] = o;
}

// ------- degree histogram, capturing per-edge ranks ----------------
__global__ void hist_kernel(const int* __restrict__ eu,
                            const int* __restrict__ ei) {
    int i = blockIdx.x * blockDim.x + threadIdx.x;
    if (i >= NE / 4) return;
    int4 a = ((const int4*)eu)[i];
    int4 b = ((const int4*)ei)[i];
    int4 ru, rv;
    ru.x = atomicAdd(&g_cnt[a.x], 1);
    ru.y = atomicAdd(&g_cnt[a.y], 1);
    ru.z = atomicAdd(&g_cnt[a.z], 1);
    ru.w = atomicAdd(&g_cnt[a.w], 1);
    rv.x = atomicAdd(&g_cnt[NU + b.x], 1);
    rv.y = atomicAdd(&g_cnt[NU + b.y], 1);
    rv.z = atomicAdd(&g_cnt[NU + b.z], 1);
    rv.w = atomicAdd(&g_cnt[NU + b.w], 1);
    ((int4*)g_rankU)[i] = ru;
    ((int4*)g_rankV)[i] = rv;
}

// -------- offsets: block scan + atomic block base; resets g_cnt ----
__global__ void offsets_kernel() {
    __shared__ int ws[32];
    __shared__ int s_base;
    int tid = threadIdx.x;
    int i = blockIdx.x * SCAN_BS + tid;
    int lane = tid & 31, wid = tid >> 5;
    int c = (i < NN) ? g_cnt[i] : 0;
    int x = c;
    #pragma unroll
    for (int off = 1; off < 32; off <<= 1) {
        int t = __shfl_up_sync(0xffffffffu, x, off);
        if (lane >= off) x += t;
    }
    if (lane == 31) ws[wid] = x;
    __syncthreads();
    if (wid == 0) {
        int y = ws[lane];
        #pragma unroll
        for (int off = 1; off < 32; off <<= 1) {
            int t = __shfl_up_sync(0xffffffffu, y, off);
            if (lane >= off) y += t;
        }
        ws[lane] = y;
    }
    __syncthreads();
    int incl = x + ((wid > 0) ? ws[wid - 1] : 0);
    if (tid == SCAN_BS - 1) s_base = atomicAdd(&g_total, incl);
    __syncthreads();
    if (i < NN) {
        int start = s_base + incl - c;
        g_range[i] = make_int2(start, start + c);
        g_dinv[i] = (c > 0) ? rsqrtf((float)c) : 0.f;
        g_cnt[i] = 0;                   // reset for next call
    }
}

// ------- fill adjacency: rank-addressed, ZERO atomics --------------
__global__ void fill_kernel(const int* __restrict__ eu,
                            const int* __restrict__ ei) {
    int i = blockIdx.x * blockDim.x + threadIdx.x;
    if (i == 0) g_total = 0;            // reset for next call
    if (i >= NE / 4) return;
    int4 a = ((const int4*)eu)[i];
    int4 b = ((const int4*)ei)[i];
    int4 ru = ((const int4*)g_rankU)[i];
    int4 rv = ((const int4*)g_rankV)[i];
    {
        int u = a.x, v = NU + b.x;
        g_adj[g_range[u].x + ru.x] = v;
        g_adj[g_range[v].x + rv.x] = u;
    }
    {
        int u = a.y, v = NU + b.y;
        g_adj[g_range[u].x + ru.y] = v;
        g_adj[g_range[v].x + rv.y] = u;
    }
    {
        int u = a.z, v = NU + b.z;
        g_adj[g_range[u].x + ru.z] = v;
        g_adj[g_range[v].x + rv.z] = u;
    }
    {
        int u = a.w, v = NU + b.w;
        g_adj[g_range[u].x + ru.w] = v;
        g_adj[g_range[v].x + rv.w] = u;
    }
}

// mark neighbors of batch nodes + the batch nodes themselves
__global__ void mark2_kernel(const int* __restrict__ uids,
                             const int* __restrict__ iids) {
    int idx = (blockIdx.x * blockDim.x + threadIdx.x) >> 5;
    if (idx >= BATCH) return;
    int lane = threadIdx.x & 31;
    int node = (lane < 16) ? uids[idx] : (NU + iids[idx]);
    int sub = lane & 15;
    int2 r = g_range[node];
    for (int p = r.x + sub; p < r.y; p += 16) {
        g_flag2[g_adj[p]] = 1;
    }
    if (sub == 0) g_flag2[node] = 1;
}

// compact + restore g_flag2 = 0
__global__ void compact2_kernel() {
    int i = blockIdx.x * blockDim.x + threadIdx.x;
    if (i >= NN) return;
    if (g_flag2[i]) {
        g_flag2[i] = 0;                 // reset for next call
        int p = atomicAdd(&g_n2, 1);
        g_list2[p] = i;
    }
}

// -------- weightless fp16 gather: pure row-sum ---------------------
__device__ __forceinline__ void sum_row8(const __half* __restrict__ prevH,
                                         int v, int sub, float* acc) {
    uint4 p = ((const uint4*)(prevH + (size_t)v * EMB))[sub];
    float2 f0 = __half22float2(*(__half2*)&p.x);
    float2 f1 = __half22float2(*(__half2*)&p.y);
    float2 f2 = __half22float2(*(__half2*)&p.z);
    float2 f3 = __half22float2(*(__half2*)&p.w);
    acc[0] += f0.x; acc[1] += f0.y;
    acc[2] += f1.x; acc[3] += f1.y;
    acc[4] += f2.x; acc[5] += f2.y;
    acc[6] += f3.x; acc[7] += f3.y;
}

__device__ __forceinline__ void gather8(int node, int sub, unsigned mask,
                                        const __half* __restrict__ prevH,
                                        float* acc) {
    int2 r = g_range[node];
    for (int base = r.x; base < r.y; base += 8) {
        int n = min(8, r.y - base);
        int dr = (sub < n) ? g_adj[base + sub] : 0;
        int j = 0;
        for (; j + 4 <= n; j += 4) {
            int v0 = __shfl_sync(mask, dr, j + 0, 8);
            int v1 = __shfl_sync(mask, dr, j + 1, 8);
            int v2 = __shfl_sync(mask, dr, j + 2, 8);
            int v3 = __shfl_sync(mask, dr, j + 3, 8);
            uint4 p0 = ((const uint4*)(prevH + (size_t)v0 * EMB))[sub];
            uint4 p1 = ((const uint4*)(prevH + (size_t)v1 * EMB))[sub];
            uint4 p2 = ((const uint4*)(prevH + (size_t)v2 * EMB))[sub];
            uint4 p3 = ((const uint4*)(prevH + (size_t)v3 * EMB))[sub];
            {
                float2 f0 = __half22float2(*(__half2*)&p0.x);
                float2 f1 = __half22float2(*(__half2*)&p0.y);
                float2 f2 = __half22float2(*(__half2*)&p0.z);
                float2 f3 = __half22float2(*(__half2*)&p0.w);
                acc[0] += f0.x; acc[1] += f0.y;
                acc[2] += f1.x; acc[3] += f1.y;
                acc[4] += f2.x; acc[5] += f2.y;
                acc[6] += f3.x; acc[7] += f3.y;
            }
            {
                float2 f0 = __half22float2(*(__half2*)&p1.x);
                float2 f1 = __half22float2(*(__half2*)&p1.y);
                float2 f2 = __half22float2(*(__half2*)&p1.z);
                float2 f3 = __half22float2(*(__half2*)&p1.w);
                acc[0] += f0.x; acc[1] += f0.y;
                acc[2] += f1.x; acc[3] += f1.y;
                acc[4] += f2.x; acc[5] += f2.y;
                acc[6] += f3.x; acc[7] += f3.y;
            }
            {
                float2 f0 = __half22float2(*(__half2*)&p2.x);
                float2 f1 = __half22float2(*(__half2*)&p2.y);
                float2 f2 = __half22float2(*(__half2*)&p2.z);
                float2 f3 = __half22float2(*(__half2*)&p2.w);
                acc[0] += f0.x; acc[1] += f0.y;
                acc[2] += f1.x; acc[3] += f1.y;
                acc[4] += f2.x; acc[5] += f2.y;
                acc[6] += f3.x; acc[7] += f3.y;
            }
            {
                float2 f0 = __half22float2(*(__half2*)&p3.x);
                float2 f1 = __half22float2(*(__half2*)&p3.y);
                float2 f2 = __half22float2(*(__half2*)&p3.z);
                float2 f3 = __half22float2(*(__half2*)&p3.w);
                acc[0] += f0.x; acc[1] += f0.y;
                acc[2] += f1.x; acc[3] += f1.y;
                acc[4] += f2.x; acc[5] += f2.y;
                acc[6] += f3.x; acc[7] += f3.y;
            }
        }
        for (; j < n; j++) {
            int v = __shfl_sync(mask, dr, j, 8);
            sum_row8(prevH, v, sub, acc);
        }
    }
}

__device__ __forceinline__ void store_half8(__half* __restrict__ nextH,
                                            int node, int sub, const float* acc,
                                            float scale) {
    __half2 o0 = __floats2half2_rn(scale * acc[0], scale * acc[1]);
    __half2 o1 = __floats2half2_rn(scale * acc[2], scale * acc[3]);
    __half2 o2 = __floats2half2_rn(scale * acc[4], scale * acc[5]);
    __half2 o3 = __floats2half2_rn(scale * acc[6], scale * acc[7]);
    uint4 o;
    o.x = *(unsigned*)&o0; o.y = *(unsigned*)&o1;
    o.z = *(unsigned*)&o2; o.w = *(unsigned*)&o3;
    ((uint4*)(nextH + (size_t)node * EMB))[sub] = o;
}

// s_{k+1}[u] = dinv[u]^2 * sum_{v in N(u)} s_k[v]
__global__ void prop_full_kernel(const __half* __restrict__ prevH,
                                 __half* __restrict__ nextH) {
    int warpId = (blockIdx.x * blockDim.x + threadIdx.x) >> 5;
    int lane = threadIdx.x & 31;
    int quad = lane >> 3;
    int sub  = lane & 7;
    int node = warpId * 4 + quad;
    if (node >= NN) return;
    unsigned mask = 0xFFu << (quad * 8);
    float acc[8] = {0.f,0.f,0.f,0.f,0.f,0.f,0.f,0.f};
    gather8(node, sub, mask, prevH, acc);
    float d = g_dinv[node];
    store_half8(nextH, node, sub, acc, d * d);
}

__global__ void prop_list_kernel(const __half* __restrict__ prevH,
                                 __half* __restrict__ nextH,
                                 const int* __restrict__ list,
                                 const int* __restrict__ count) {
    int warpId = (blockIdx.x * blockDim.x + threadIdx.x) >> 5;
    int lane = threadIdx.x & 31;
    int cnt = __shfl_sync(0xffffffffu, (lane == 0) ? *count : 0, 0);
    int quad = lane >> 3;
    int sub  = lane & 7;
    int idx = warpId * 4 + quad;
    if (idx >= cnt) return;
    int node = list[idx];
    unsigned mask = 0xFFu << (quad * 8);
    float acc[8] = {0.f,0.f,0.f,0.f,0.f,0.f,0.f,0.f};
    gather8(node, sub, mask, prevH, acc);
    float d = g_dinv[node];
    store_half8(nextH, node, sub, acc, d * d);
}

// --------------- fused layer-3 + score (+ resets g_n2) -------------
// e1 = s1/dinv, e2 = s2/dinv, e3 = dinv * sum s2[v]
__global__ void score_kernel(const int* __restrict__ uids,
                             const int* __restrict__ iids,
                             const float* __restrict__ ue,
                             const float* __restrict__ ie,
                             float* __restrict__ out) {
    int gt = blockIdx.x * blockDim.x + threadIdx.x;
    if (gt == 0) g_n2 = 0;              // reset for next call
    int grpG = gt >> 3;
    int sub  = gt & 7;
    int pair = grpG >> 1;
    int side = grpG & 1;
    if (pair >= BATCH) return;
    int lane = threadIdx.x & 31;
    int grp = lane >> 3;
    unsigned gmask = 0xFFu << (grp * 8);

    int node;
    const float4* r0;
    if (side == 0) {
        int u = uids[pair];
        node = u;
        r0 = (const float4*)(ue + (size_t)u * EMB);
    } else {
        int v = iids[pair];
        node = NU + v;
        r0 = (const float4*)(ie + (size_t)v * EMB);
    }

    float w0 = g_w[0], w1 = g_w[1], w2 = g_w[2], w3 = g_w[3];
    float d = g_dinv[node];
    float inv = (d > 0.f) ? 1.f / d : 0.f;
    float w1i = w1 * inv, w2i = w2 * inv, w3d = w3 * d;

    float a3[8] = {0.f,0.f,0.f,0.f,0.f,0.f,0.f,0.f};
    gather8(node, sub, gmask, g_h2, a3);

    float4 pa = r0[sub * 2];
    float4 pb = r0[sub * 2 + 1];
    uint4 x1 = ((const uint4*)(g_h1 + (size_t)node * EMB))[sub];
    uint4 x2 = ((const uint4*)(g_h2 + (size_t)node * EMB))[sub];
    float2 l1a = __half22float2(*(__half2*)&x1.x);
    float2 l1b = __half22float2(*(__half2*)&x1.y);
    float2 l1c = __half22float2(*(__half2*)&x1.z);
    float2 l1d = __half22float2(*(__half2*)&x1.w);
    float2 l2a = __half22float2(*(__half2*)&x2.x);
    float2 l2b = __half22float2(*(__half2*)&x2.y);
    float2 l2c = __half22float2(*(__half2*)&x2.z);
    float2 l2d = __half22float2(*(__half2*)&x2.w);

    float f[8];
    f[0] = w0 * pa.x + w1i * l1a.x + w2i * l2a.x + w3d * a3[0];
    f[1] = w0 * pa.y + w1i * l1a.y + w2i * l2a.y + w3d * a3[1];
    f[2] = w0 * pa.z + w1i * l1b.x + w2i * l2b.x + w3d * a3[2];
    f[3] = w0 * pa.w + w1i * l1b.y + w2i * l2b.y + w3d * a3[3];
    f[4] = w0 * pb.x + w1i * l1c.x + w2i * l2c.x + w3d * a3[4];
    f[5] = w0 * pb.y + w1i * l1c.y + w2i * l2c.y + w3d * a3[5];
    f[6] = w0 * pb.z + w1i * l1d.x + w2i * l2d.x + w3d * a3[6];
    f[7] = w0 * pb.w + w1i * l1d.y + w2i * l2d.y + w3d * a3[7];

    float dp = 0.f;
    #pragma unroll
    for (int k = 0; k < 8; k++) {
        float other = __shfl_xor_sync(0xffffffffu, f[k], 8);
        dp += f[k] * other;
    }
    dp += __shfl_down_sync(0xffffffffu, dp, 4, 8);
    dp += __shfl_down_sync(0xffffffffu, dp, 2, 8);
    dp += __shfl_down_sync(0xffffffffu, dp, 1, 8);
    if (side == 0 && sub == 0) out[pair] = dp;
}

// ------------------------- launcher --------------------------------
extern "C" void kernel_launch(void* const* d_in, const int* in_sizes, int n_in,
                              void* d_out, int out_size) {
    const float* user_emb = (const float*)d_in[0];
    const float* item_emb = (const float*)d_in[1];
    const float* layer_w  = (const float*)d_in[2];
    const int*   eu       = (const int*)d_in[3];
    const int*   ei       = (const int*)d_in[4];
    const int*   uids     = (const int*)d_in[5];
    const int*   iids     = (const int*)d_in[6];
    float*       out      = (float*)d_out;
    (void)in_sizes; (void)n_in; (void)out_size;

    __half *h0, *h1, *h2;
    int *list2, *n2;
    cudaGetSymbolAddress((void**)&h0, g_h0);
    cudaGetSymbolAddress((void**)&h1, g_h1);
    cudaGetSymbolAddress((void**)&h2, g_h2);
    cudaGetSymbolAddress((void**)&list2, g_list2);
    cudaGetSymbolAddress((void**)&n2, g_n2);

    cudaStream_t s1;
    cudaStreamCreateWithFlags(&s1, cudaStreamNonBlocking);
    cudaEvent_t evFork, evOff, evScale, evFill, evMark;
    cudaEventCreateWithFlags(&evFork, cudaEventDisableTiming);
    cudaEventCreateWithFlags(&evOff, cudaEventDisableTiming);
    cudaEventCreateWithFlags(&evScale, cudaEventDisableTiming);
    cudaEventCreateWithFlags(&evFill, cudaEventDisableTiming);
    cudaEventCreateWithFlags(&evMark, cudaEventDisableTiming);

    // ---- side stream: fp16 conversion + softmax ----
    cudaEventRecord(evFork, 0);
    cudaStreamWaitEvent(s1, evFork, 0);
    const size_t CONV_T = (size_t)NN * EMB / 8;
    const int CONV_B = (int)((CONV_T + 255) / 256);
    conv_kernel<<<CONV_B, 256, 0, s1>>>(user_emb, item_emb, layer_w);

    // ---- CSR chain on main stream (g_cnt already zero) ----
    hist_kernel<<<(NE / 4 + 255) / 256, 256>>>(eu, ei);
    offsets_kernel<<<NSB, SCAN_BS>>>();
    cudaEventRecord(evOff, 0);
    fill_kernel<<<(NE / 4 + 255) / 256, 256>>>(eu, ei);
    cudaEventRecord(evFill, 0);

    // ---- side stream: scale h0 by dinv (needs conv + offsets) ----
    cudaStreamWaitEvent(s1, evOff, 0);
    scale_kernel<<<CONV_B, 256, 0, s1>>>();
    cudaEventRecord(evScale, s1);

    // ---- side stream: frontier (needs fill; overlaps prop_full) ----
    cudaStreamWaitEvent(s1, evFill, 0);
    mark2_kernel<<<(BATCH * 32 + 255) / 256, 256, 0, s1>>>(uids, iids);
    compact2_kernel<<<(NN + 255) / 256, 256, 0, s1>>>();
    cudaEventRecord(evMark, s1);

    // ---- propagation (scaled space) ----
    cudaStreamWaitEvent(0, evScale, 0);
    const int FULL_BLOCKS = ((NN + 3) / 4 * 32 + 255) / 256;
    prop_full_kernel<<<FULL_BLOCKS, 256>>>(h0, h1);
    cudaStreamWaitEvent(0, evMark, 0);
    prop_list_kernel<<<FULL_BLOCKS, 256>>>(h1, h2, list2, n2);

    // ---- fused layer-3 + scores (also resets g_n2) ----
    score_kernel<<<(BATCH * 16 + 255) / 256, 256>>>(uids, iids, user_emb, item_emb, out);

    cudaEventDestroy(evFork);
    cudaEventDestroy(evOff);
    cudaEventDestroy(evScale);
    cudaEventDestroy(evFill);
    cudaEventDestroy(evMark);
    cudaStreamDestroy(s1);
}

// round 15
// speedup vs baseline: 1.0749x; 1.0060x over previous
#include <cuda_runtime.h>
#include <cuda_fp16.h>

#define NU 100000
#define NI 200000
#define NN 300000          // NU + NI
#define EMB 64
#define NE 1000000
#define BATCH 16384

#define SCAN_BS 1024
#define NSB ((NN + SCAN_BS - 1) / SCAN_BS)   // 293
#define NE4 (NE / 4)                          // 250000 int4 groups

// -------- scratch (device globals; zero-initialized at load) -------
// INVARIANT: every kernel_launch leaves g_cnt, g_flag2, g_n2, g_total
// zeroed (consume-and-reset), so no zero pass is needed at the head.
__device__ int    g_cnt[NN];
__device__ int    g_total;                 // adjacency cursor (offsets kernel)
__device__ int2   g_range[NN];             // {start, end} per node
__device__ float  g_dinv[NN];
__device__ float  g_w[4];
__device__ int    g_rankU[NE];             // edge rank in user list (from hist)
__device__ int    g_rankV[NE];             // edge rank in item list (from hist)
__device__ int    g_adj[2 * NE];           // dst node only (weightless)
__device__ __half g_h0[(size_t)NN * EMB];  // fp16 inputs -> scaled s0 in place
__device__ __half g_h1[(size_t)NN * EMB];  // s1
__device__ __half g_h2[(size_t)NN * EMB];  // s2
__device__ int    g_flag2[NN];
__device__ int    g_list2[NN];
__device__ int    g_n2;

// ------- fp32 -> fp16 conversion + softmax (stream s1) -------------
__global__ void conv_kernel(const float* __restrict__ ue,
                            const float* __restrict__ ie,
                            const float* __restrict__ lw) {
    size_t i = (size_t)blockIdx.x * blockDim.x + threadIdx.x;
    const size_t total = (size_t)NN * EMB / 8;
    if (i == 0) {
        float m = lw[0];
        for (int k = 1; k < 4; k++) m = fmaxf(m, lw[k]);
        float s = 0.f, e[4];
        for (int k = 0; k < 4; k++) { e[k] = expf(lw[k] - m); s += e[k]; }
        for (int k = 0; k < 4; k++) g_w[k] = e[k] / s;
    }
    if (i >= total) return;
    size_t base = i * 8;
    const float4* s = (base < (size_t)NU * EMB)
        ? (const float4*)(ue + base)
        : (const float4*)(ie + (base - (size_t)NU * EMB));
    float4 a = s[0], b = s[1];
    __half2 c0 = __floats2half2_rn(a.x, a.y);
    __half2 c1 = __floats2half2_rn(a.z, a.w);
    __half2 c2 = __floats2half2_rn(b.x, b.y);
    __half2 c3 = __floats2half2_rn(b.z, b.w);
    uint4 o;
    o.x = *(unsigned*)&c0; o.y = *(unsigned*)&c1;
    o.z = *(unsigned*)&c2; o.w = *(unsigned*)&c3;
    ((uint4*)g_h0)[i] = o;
}

// ------- in-place scale: h0 *= dinv[node]  (stream s1) -------------
__global__ void scale_kernel() {
    size_t i = (size_t)blockIdx.x * blockDim.x + threadIdx.x;
    const size_t total = (size_t)NN * EMB / 8;
    if (i >= total) return;
    int node = (int)(i >> 3);
    float d = g_dinv[node];
    uint4 x = ((uint4*)g_h0)[i];
    float2 f0 = __half22float2(*(__half2*)&x.x);
    float2 f1 = __half22float2(*(__half2*)&x.y);
    float2 f2 = __half22float2(*(__half2*)&x.z);
    float2 f3 = __half22float2(*(__half2*)&x.w);
    __half2 o0 = __floats2half2_rn(d * f0.x, d * f0.y);
    __half2 o1 = __floats2half2_rn(d * f1.x, d * f1.y);
    __half2 o2 = __floats2half2_rn(d * f2.x, d * f2.y);
    __half2 o3 = __floats2half2_rn(d * f3.x, d * f3.y);
    uint4 o;
    o.x = *(unsigned*)&o0; o.y = *(unsigned*)&o1;
    o.z = *(unsigned*)&o2; o.w = *(unsigned*)&o3;
    ((uint4*)g_h0)[i] = o;
}

// ------- degree histogram half-range, capturing ranks --------------
__global__ void hist_kernel(const int* __restrict__ eu,
                            const int* __restrict__ ei,
                            int lo4, int hi4) {
    int i = lo4 + blockIdx.x * blockDim.x + threadIdx.x;
    if (i >= hi4) return;
    int4 a = ((const int4*)eu)[i];
    int4 b = ((const int4*)ei)[i];
    int4 ru, rv;
    ru.x = atomicAdd(&g_cnt[a.x], 1);
    ru.y = atomicAdd(&g_cnt[a.y], 1);
    ru.z = atomicAdd(&g_cnt[a.z], 1);
    ru.w = atomicAdd(&g_cnt[a.w], 1);
    rv.x = atomicAdd(&g_cnt[NU + b.x], 1);
    rv.y = atomicAdd(&g_cnt[NU + b.y], 1);
    rv.z = atomicAdd(&g_cnt[NU + b.z], 1);
    rv.w = atomicAdd(&g_cnt[NU + b.w], 1);
    ((int4*)g_rankU)[i] = ru;
    ((int4*)g_rankV)[i] = rv;
}

// -------- offsets: block scan + atomic block base; resets g_cnt ----
__global__ void offsets_kernel() {
    __shared__ int ws[32];
    __shared__ int s_base;
    int tid = threadIdx.x;
    int i = blockIdx.x * SCAN_BS + tid;
    int lane = tid & 31, wid = tid >> 5;
    int c = (i < NN) ? g_cnt[i] : 0;
    int x = c;
    #pragma unroll
    for (int off = 1; off < 32; off <<= 1) {
        int t = __shfl_up_sync(0xffffffffu, x, off);
        if (lane >= off) x += t;
    }
    if (lane == 31) ws[wid] = x;
    __syncthreads();
    if (wid == 0) {
        int y = ws[lane];
        #pragma unroll
        for (int off = 1; off < 32; off <<= 1) {
            int t = __shfl_up_sync(0xffffffffu, y, off);
            if (lane >= off) y += t;
        }
        ws[lane] = y;
    }
    __syncthreads();
    int incl = x + ((wid > 0) ? ws[wid - 1] : 0);
    if (tid == SCAN_BS - 1) s_base = atomicAdd(&g_total, incl);
    __syncthreads();
    if (i < NN) {
        int start = s_base + incl - c;
        g_range[i] = make_int2(start, start + c);
        g_dinv[i] = (c > 0) ? rsqrtf((float)c) : 0.f;
        g_cnt[i] = 0;                   // reset for next call
    }
}

// ------- fill adjacency half-range: rank-addressed, no atomics -----
__global__ void fill_kernel(const int* __restrict__ eu,
                            const int* __restrict__ ei,
                            int lo4, int hi4, int do_reset) {
    int i = lo4 + blockIdx.x * blockDim.x + threadIdx.x;
    if (do_reset && i == lo4 && threadIdx.x == 0 && blockIdx.x == 0)
        g_total = 0;                    // reset for next call
    if (i >= hi4) return;
    int4 a = ((const int4*)eu)[i];
    int4 b = ((const int4*)ei)[i];
    int4 ru = ((const int4*)g_rankU)[i];
    int4 rv = ((const int4*)g_rankV)[i];
    {
        int u = a.x, v = NU + b.x;
        g_adj[g_range[u].x + ru.x] = v;
        g_adj[g_range[v].x + rv.x] = u;
    }
    {
        int u = a.y, v = NU + b.y;
        g_adj[g_range[u].x + ru.y] = v;
        g_adj[g_range[v].x + rv.y] = u;
    }
    {
        int u = a.z, v = NU + b.z;
        g_adj[g_range[u].x + ru.z] = v;
        g_adj[g_range[v].x + rv.z] = u;
    }
    {
        int u = a.w, v = NU + b.w;
        g_adj[g_range[u].x + ru.w] = v;
        g_adj[g_range[v].x + rv.w] = u;
    }
}

// mark neighbors of batch nodes + the batch nodes themselves
__global__ void mark2_kernel(const int* __restrict__ uids,
                             const int* __restrict__ iids) {
    int idx = (blockIdx.x * blockDim.x + threadIdx.x) >> 5;
    if (idx >= BATCH) return;
    int lane = threadIdx.x & 31;
    int node = (lane < 16) ? uids[idx] : (NU + iids[idx]);
    int sub = lane & 15;
    int2 r = g_range[node];
    for (int p = r.x + sub; p < r.y; p += 16) {
        g_flag2[g_adj[p]] = 1;
    }
    if (sub == 0) g_flag2[node] = 1;
}

// compact + restore g_flag2 = 0
__global__ void compact2_kernel() {
    int i = blockIdx.x * blockDim.x + threadIdx.x;
    if (i >= NN) return;
    if (g_flag2[i]) {
        g_flag2[i] = 0;                 // reset for next call
        int p = atomicAdd(&g_n2, 1);
        g_list2[p] = i;
    }
}

// -------- weightless fp16 gather: pure row-sum ---------------------
__device__ __forceinline__ void sum_row8(const __half* __restrict__ prevH,
                                         int v, int sub, float* acc) {
    uint4 p = ((const uint4*)(prevH + (size_t)v * EMB))[sub];
    float2 f0 = __half22float2(*(__half2*)&p.x);
    float2 f1 = __half22float2(*(__half2*)&p.y);
    float2 f2 = __half22float2(*(__half2*)&p.z);
    float2 f3 = __half22float2(*(__half2*)&p.w);
    acc[0] += f0.x; acc[1] += f0.y;
    acc[2] += f1.x; acc[3] += f1.y;
    acc[4] += f2.x; acc[5] += f2.y;
    acc[6] += f3.x; acc[7] += f3.y;
}

__device__ __forceinline__ void gather8(int node, int sub, unsigned mask,
                                        const __half* __restrict__ prevH,
                                        float* acc) {
    int2 r = g_range[node];
    for (int base = r.x; base < r.y; base += 8) {
        int n = min(8, r.y - base);
        int dr = (sub < n) ? g_adj[base + sub] : 0;
        int j = 0;
        for (; j + 4 <= n; j += 4) {
            int v0 = __shfl_sync(mask, dr, j + 0, 8);
            int v1 = __shfl_sync(mask, dr, j + 1, 8);
            int v2 = __shfl_sync(mask, dr, j + 2, 8);
            int v3 = __shfl_sync(mask, dr, j + 3, 8);
            uint4 p0 = ((const uint4*)(prevH + (size_t)v0 * EMB))[sub];
            uint4 p1 = ((const uint4*)(prevH + (size_t)v1 * EMB))[sub];
            uint4 p2 = ((const uint4*)(prevH + (size_t)v2 * EMB))[sub];
            uint4 p3 = ((const uint4*)(prevH + (size_t)v3 * EMB))[sub];
            {
                float2 f0 = __half22float2(*(__half2*)&p0.x);
                float2 f1 = __half22float2(*(__half2*)&p0.y);
                float2 f2 = __half22float2(*(__half2*)&p0.z);
                float2 f3 = __half22float2(*(__half2*)&p0.w);
                acc[0] += f0.x; acc[1] += f0.y;
                acc[2] += f1.x; acc[3] += f1.y;
                acc[4] += f2.x; acc[5] += f2.y;
                acc[6] += f3.x; acc[7] += f3.y;
            }
            {
                float2 f0 = __half22float2(*(__half2*)&p1.x);
                float2 f1 = __half22float2(*(__half2*)&p1.y);
                float2 f2 = __half22float2(*(__half2*)&p1.z);
                float2 f3 = __half22float2(*(__half2*)&p1.w);
                acc[0] += f0.x; acc[1] += f0.y;
                acc[2] += f1.x; acc[3] += f1.y;
                acc[4] += f2.x; acc[5] += f2.y;
                acc[6] += f3.x; acc[7] += f3.y;
            }
            {
                float2 f0 = __half22float2(*(__half2*)&p2.x);
                float2 f1 = __half22float2(*(__half2*)&p2.y);
                float2 f2 = __half22float2(*(__half2*)&p2.z);
                float2 f3 = __half22float2(*(__half2*)&p2.w);
                acc[0] += f0.x; acc[1] += f0.y;
                acc[2] += f1.x; acc[3] += f1.y;
                acc[4] += f2.x; acc[5] += f2.y;
                acc[6] += f3.x; acc[7] += f3.y;
            }
            {
                float2 f0 = __half22float2(*(__half2*)&p3.x);
                float2 f1 = __half22float2(*(__half2*)&p3.y);
                float2 f2 = __half22float2(*(__half2*)&p3.z);
                float2 f3 = __half22float2(*(__half2*)&p3.w);
                acc[0] += f0.x; acc[1] += f0.y;
                acc[2] += f1.x; acc[3] += f1.y;
                acc[4] += f2.x; acc[5] += f2.y;
                acc[6] += f3.x; acc[7] += f3.y;
            }
        }
        for (; j < n; j++) {
            int v = __shfl_sync(mask, dr, j, 8);
            sum_row8(prevH, v, sub, acc);
        }
    }
}

__device__ __forceinline__ void store_half8(__half* __restrict__ nextH,
                                            int node, int sub, const float* acc,
                                            float scale) {
    __half2 o0 = __floats2half2_rn(scale * acc[0], scale * acc[1]);
    __half2 o1 = __floats2half2_rn(scale * acc[2], scale * acc[3]);
    __half2 o2 = __floats2half2_rn(scale * acc[4], scale * acc[5]);
    __half2 o3 = __floats2half2_rn(scale * acc[6], scale * acc[7]);
    uint4 o;
    o.x = *(unsigned*)&o0; o.y = *(unsigned*)&o1;
    o.z = *(unsigned*)&o2; o.w = *(unsigned*)&o3;
    ((uint4*)(nextH + (size_t)node * EMB))[sub] = o;
}

// s_{k+1}[u] = dinv[u]^2 * sum_{v in N(u)} s_k[v]
__global__ void prop_full_kernel(const __half* __restrict__ prevH,
                                 __half* __restrict__ nextH) {
    int warpId = (blockIdx.x * blockDim.x + threadIdx.x) >> 5;
    int lane = threadIdx.x & 31;
    int quad = lane >> 3;
    int sub  = lane & 7;
    int node = warpId * 4 + quad;
    if (node >= NN) return;
    unsigned mask = 0xFFu << (quad * 8);
    float acc[8] = {0.f,0.f,0.f,0.f,0.f,0.f,0.f,0.f};
    gather8(node, sub, mask, prevH, acc);
    float d = g_dinv[node];
    store_half8(nextH, node, sub, acc, d * d);
}

__global__ void prop_list_kernel(const __half* __restrict__ prevH,
                                 __half* __restrict__ nextH,
                                 const int* __restrict__ list,
                                 const int* __restrict__ count) {
    int warpId = (blockIdx.x * blockDim.x + threadIdx.x) >> 5;
    int lane = threadIdx.x & 31;
    int cnt = __shfl_sync(0xffffffffu, (lane == 0) ? *count : 0, 0);
    int quad = lane >> 3;
    int sub  = lane & 7;
    int idx = warpId * 4 + quad;
    if (idx >= cnt) return;
    int node = list[idx];
    unsigned mask = 0xFFu << (quad * 8);
    float acc[8] = {0.f,0.f,0.f,0.f,0.f,0.f,0.f,0.f};
    gather8(node, sub, mask, prevH, acc);
    float d = g_dinv[node];
    store_half8(nextH, node, sub, acc, d * d);
}

// --------------- fused layer-3 + score (+ resets g_n2) -------------
__global__ void score_kernel(const int* __restrict__ uids,
                             const int* __restrict__ iids,
                             const float* __restrict__ ue,
                             const float* __restrict__ ie,
                             float* __restrict__ out) {
    int gt = blockIdx.x * blockDim.x + threadIdx.x;
    if (gt == 0) g_n2 = 0;              // reset for next call
    int grpG = gt >> 3;
    int sub  = gt & 7;
    int pair = grpG >> 1;
    int side = grpG & 1;
    if (pair >= BATCH) return;
    int lane = threadIdx.x & 31;
    int grp = lane >> 3;
    unsigned gmask = 0xFFu << (grp * 8);

    int node;
    const float4* r0;
    if (side == 0) {
        int u = uids[pair];
        node = u;
        r0 = (const float4*)(ue + (size_t)u * EMB);
    } else {
        int v = iids[pair];
        node = NU + v;
        r0 = (const float4*)(ie + (size_t)v * EMB);
    }

    float w0 = g_w[0], w1 = g_w[1], w2 = g_w[2], w3 = g_w[3];
    float d = g_dinv[node];
    float inv = (d > 0.f) ? 1.f / d : 0.f;
    float w1i = w1 * inv, w2i = w2 * inv, w3d = w3 * d;

    float a3[8] = {0.f,0.f,0.f,0.f,0.f,0.f,0.f,0.f};
    gather8(node, sub, gmask, g_h2, a3);

    float4 pa = r0[sub * 2];
    float4 pb = r0[sub * 2 + 1];
    uint4 x1 = ((const uint4*)(g_h1 + (size_t)node * EMB))[sub];
    uint4 x2 = ((const uint4*)(g_h2 + (size_t)node * EMB))[sub];
    float2 l1a = __half22float2(*(__half2*)&x1.x);
    float2 l1b = __half22float2(*(__half2*)&x1.y);
    float2 l1c = __half22float2(*(__half2*)&x1.z);
    float2 l1d = __half22float2(*(__half2*)&x1.w);
    float2 l2a = __half22float2(*(__half2*)&x2.x);
    float2 l2b = __half22float2(*(__half2*)&x2.y);
    float2 l2c = __half22float2(*(__half2*)&x2.z);
    float2 l2d = __half22float2(*(__half2*)&x2.w);

    float f[8];
    f[0] = w0 * pa.x + w1i * l1a.x + w2i * l2a.x + w3d * a3[0];
    f[1] = w0 * pa.y + w1i * l1a.y + w2i * l2a.y + w3d * a3[1];
    f[2] = w0 * pa.z + w1i * l1b.x + w2i * l2b.x + w3d * a3[2];
    f[3] = w0 * pa.w + w1i * l1b.y + w2i * l2b.y + w3d * a3[3];
    f[4] = w0 * pb.x + w1i * l1c.x + w2i * l2c.x + w3d * a3[4];
    f[5] = w0 * pb.y + w1i * l1c.y + w2i * l2c.y + w3d * a3[5];
    f[6] = w0 * pb.z + w1i * l1d.x + w2i * l2d.x + w3d * a3[6];
    f[7] = w0 * pb.w + w1i * l1d.y + w2i * l2d.y + w3d * a3[7];

    float dp = 0.f;
    #pragma unroll
    for (int k = 0; k < 8; k++) {
        float other = __shfl_xor_sync(0xffffffffu, f[k], 8);
        dp += f[k] * other;
    }
    dp += __shfl_down_sync(0xffffffffu, dp, 4, 8);
    dp += __shfl_down_sync(0xffffffffu, dp, 2, 8);
    dp += __shfl_down_sync(0xffffffffu, dp, 1, 8);
    if (side == 0 && sub == 0) out[pair] = dp;
}

// ------------------------- launcher --------------------------------
extern "C" void kernel_launch(void* const* d_in, const int* in_sizes, int n_in,
                              void* d_out, int out_size) {
    const float* user_emb = (const float*)d_in[0];
    const float* item_emb = (const float*)d_in[1];
    const float* layer_w  = (const float*)d_in[2];
    const int*   eu       = (const int*)d_in[3];
    const int*   ei       = (const int*)d_in[4];
    const int*   uids     = (const int*)d_in[5];
    const int*   iids     = (const int*)d_in[6];
    float*       out      = (float*)d_out;
    (void)in_sizes; (void)n_in; (void)out_size;

    __half *h0, *h1, *h2;
    int *list2, *n2;
    cudaGetSymbolAddress((void**)&h0, g_h0);
    cudaGetSymbolAddress((void**)&h1, g_h1);
    cudaGetSymbolAddress((void**)&h2, g_h2);
    cudaGetSymbolAddress((void**)&list2, g_list2);
    cudaGetSymbolAddress((void**)&n2, g_n2);

    cudaStream_t s1, s2;
    cudaStreamCreateWithFlags(&s1, cudaStreamNonBlocking);
    cudaStreamCreateWithFlags(&s2, cudaStreamNonBlocking);
    cudaEvent_t evFork, evHistB, evOff, evScale, evFillA, evFillB, evMark;
    cudaEventCreateWithFlags(&evFork, cudaEventDisableTiming);
    cudaEventCreateWithFlags(&evHistB, cudaEventDisableTiming);
    cudaEventCreateWithFlags(&evOff, cudaEventDisableTiming);
    cudaEventCreateWithFlags(&evScale, cudaEventDisableTiming);
    cudaEventCreateWithFlags(&evFillA, cudaEventDisableTiming);
    cudaEventCreateWithFlags(&evFillB, cudaEventDisableTiming);
    cudaEventCreateWithFlags(&evMark, cudaEventDisableTiming);

    const int HALF4 = NE4 / 2;               // 125000 int4 groups per half
    const int HB = (HALF4 + 255) / 256;

    // ---- fork ----
    cudaEventRecord(evFork, 0);
    cudaStreamWaitEvent(s1, evFork, 0);
    cudaStreamWaitEvent(s2, evFork, 0);

    // s1: conv (DRAM-bound) + later scale
    const size_t CONV_T = (size_t)NN * EMB / 8;
    const int CONV_B = (int)((CONV_T + 255) / 256);
    conv_kernel<<<CONV_B, 256, 0, s1>>>(user_emb, item_emb, layer_w);

    // hist split: main does first half, s2 second half (concurrent)
    hist_kernel<<<HB, 256>>>(eu, ei, 0, HALF4);
    hist_kernel<<<HB, 256, 0, s2>>>(eu, ei, HALF4, NE4);
    cudaEventRecord(evHistB, s2);

    // offsets on main needs both hist halves
    cudaStreamWaitEvent(0, evHistB, 0);
    offsets_kernel<<<NSB, SCAN_BS>>>();
    cudaEventRecord(evOff, 0);

    // fill split: main first half (owns g_total reset), s2 second half
    fill_kernel<<<HB, 256>>>(eu, ei, 0, HALF4, 1);
    cudaEventRecord(evFillA, 0);
    cudaStreamWaitEvent(s2, evOff, 0);
    fill_kernel<<<HB, 256, 0, s2>>>(eu, ei, HALF4, NE4, 0);
    cudaEventRecord(evFillB, s2);

    // s1: scale h0 by dinv (needs conv done + offsets)
    cudaStreamWaitEvent(s1, evOff, 0);
    scale_kernel<<<CONV_B, 256, 0, s1>>>();
    cudaEventRecord(evScale, s1);

    // s2: frontier (needs both fill halves); overlaps prop_full
    cudaStreamWaitEvent(s2, evFillA, 0);
    mark2_kernel<<<(BATCH * 32 + 255) / 256, 256, 0, s2>>>(uids, iids);
    compact2_kernel<<<(NN + 255) / 256, 256, 0, s2>>>();
    cudaEventRecord(evMark, s2);

    // main: propagation (needs both fills + scale)
    cudaStreamWaitEvent(0, evFillB, 0);
    cudaStreamWaitEvent(0, evScale, 0);
    const int FULL_BLOCKS = ((NN + 3) / 4 * 32 + 255) / 256;
    prop_full_kernel<<<FULL_BLOCKS, 256>>>(h0, h1);
    cudaStreamWaitEvent(0, evMark, 0);
    prop_list_kernel<<<FULL_BLOCKS, 256>>>(h1, h2, list2, n2);

    // main: fused layer-3 + scores (also resets g_n2)
    score_kernel<<<(BATCH * 16 + 255) / 256, 256>>>(uids, iids, user_emb, item_emb, out);

    cudaEventDestroy(evFork);
    cudaEventDestroy(evHistB);
    cudaEventDestroy(evOff);
    cudaEventDestroy(evScale);
    cudaEventDestroy(evFillA);
    cudaEventDestroy(evFillB);
    cudaEventDestroy(evMark);
    cudaStreamDestroy(s1);
    cudaStreamDestroy(s2);
}